// round 2
// baseline (speedup 1.0000x reference)
#include <cuda_runtime.h>
#include <cuda_bf16.h>
#include <math.h>
#include <stdint.h>

// ---------------- constants ----------------
#define BB   16
#define NN_  512
#define LL   1024
#define CD   128
#define GD   64
#define NH   4
#define LAT  128

// ---------------- scratch ----------------
__device__ float g_av       [BB*NN_*CD];
__device__ float g_wh1      [BB*NN_*(GD*NH)];
__device__ float g_multi    [BB*NN_*(GD*NH)];
__device__ float g_wh2      [BB*NN_*CD];
__device__ float g_x        [BB*NN_*CD];
__device__ float g_atoms_vec[BB*NN_*LAT];
__device__ float g_av_att   [BB*NN_*LAT];
__device__ float g_src1[BB*NH*NN_], g_dst1[BB*NH*NN_];
__device__ float g_src2[BB*NN_],    g_dst2[BB*NN_];
__device__ float g_cnvA[BB*LL*CD];
__device__ float g_cnvB[BB*LL*CD];
__device__ float g_T[30*11*CD];
__device__ float g_Wcat  [CD*(GD*NH)];
__device__ float g_WcompT[CD*LAT];
__device__ float g_WattT [LAT*LAT];
__device__ float g_comp[BB*LAT], g_prot[BB*LAT];
__device__ float g_pp[BB*8*128];
__device__ float g_pm[BB*8];

__device__ __forceinline__ float lrelu(float x){ return x > 0.f ? x : 0.2f*x; }
__device__ __forceinline__ float eluf (float x){ return x > 0.f ? x : (__expf(x) - 1.f); }

// ---------------- f32x2 packed helpers ----------------
__device__ __forceinline__ uint64_t pk2(float x){
    uint32_t xi = __float_as_uint(x);
    uint64_t r; asm("mov.b64 %0, {%1, %1};" : "=l"(r) : "r"(xi)); return r;
}
__device__ __forceinline__ uint64_t pk2f(float x, float y){
    uint32_t xi = __float_as_uint(x), yi = __float_as_uint(y);
    uint64_t r; asm("mov.b64 %0, {%1, %2};" : "=l"(r) : "r"(xi), "r"(yi)); return r;
}
__device__ __forceinline__ void fma2(uint64_t& d, uint64_t a, uint64_t b){
    asm("fma.rn.f32x2 %0, %1, %2, %0;" : "+l"(d) : "l"(a), "l"(b));
}
__device__ __forceinline__ float2 up2(uint64_t v){
    uint32_t lo, hi; asm("mov.b64 {%0, %1}, %2;" : "=r"(lo), "=r"(hi) : "l"(v));
    return make_float2(__uint_as_float(lo), __uint_as_float(hi));
}

// ---------------- tiny prep kernels ----------------
__global__ void k_pack_wgat(const float* __restrict__ W_gat){
    int k = blockIdx.x, c = threadIdx.x;
    int h = c >> 6, f = c & 63;
    g_Wcat[k*256 + c] = W_gat[((h*128) + k)*64 + f];
}

__global__ void k_transp128(const float* __restrict__ in, float* __restrict__ out){
    int k = blockIdx.x, c = threadIdx.x;
    out[k*128 + c] = in[c*128 + k];
}

__global__ void k_table(const float* __restrict__ conv_w, const float* __restrict__ E_amino){
    int dl = blockIdx.x, a = blockIdx.y, f = threadIdx.x;
    float acc = 0.f;
    #pragma unroll
    for (int df = 0; df < 11; ++df) {
        int fi = f + df - 5;
        if (fi >= 0 && fi < 128) acc += conv_w[dl*11 + df] * E_amino[a*128 + fi];
    }
    g_T[(a*11 + dl)*128 + f] = acc;
}

__global__ void k_embed_atoms(const int* __restrict__ atoms, const float* __restrict__ E_atom){
    int row = blockIdx.x, f = threadIdx.x;
    g_av[(size_t)row*128 + f] = E_atom[atoms[row]*128 + f];
}

// ---------------- tiled fp32 GEMM with f32x2: C = act(A@B + bias) ----------------
// tile 64 rows x 128 cols, block 256; thread: 4 rows x 8 cols (4 f32x2 pairs)
__global__ void __launch_bounds__(256) k_gemm(
    const float* __restrict__ A, const float* __restrict__ B,
    const float* __restrict__ bias, float* __restrict__ C,
    int M, int N, int K, int act)
{
    __shared__ __align__(16) float As[16][68];   // [kk][row]
    __shared__ __align__(16) float Bs[16][132];  // [kk][col]
    const int m0 = blockIdx.x*64, n0 = blockIdx.y*128;
    const int tid = threadIdx.x;
    const int ti = tid & 15, tj = tid >> 4;      // 16 col-groups, 16 row-groups
    uint64_t acc[4][4];
    #pragma unroll
    for (int r=0;r<4;++r){ acc[r][0]=0; acc[r][1]=0; acc[r][2]=0; acc[r][3]=0; }

    const int lrow = tid >> 2, lkk = (tid & 3) * 4;     // A load map
    const int bcol = (tid & 31) * 4, bkk = tid >> 5;    // B load map

    for (int k0 = 0; k0 < K; k0 += 16) {
        __syncthreads();
        {
            float4 v = *(const float4*)&A[(size_t)(m0 + lrow)*K + k0 + lkk];
            As[lkk+0][lrow]=v.x; As[lkk+1][lrow]=v.y; As[lkk+2][lrow]=v.z; As[lkk+3][lrow]=v.w;
        }
        *(float4*)&Bs[bkk  ][bcol] = *(const float4*)&B[(size_t)(k0 + bkk  )*N + n0 + bcol];
        *(float4*)&Bs[bkk+8][bcol] = *(const float4*)&B[(size_t)(k0 + bkk+8)*N + n0 + bcol];
        __syncthreads();
        #pragma unroll
        for (int kk = 0; kk < 16; ++kk) {
            const uint64_t* bp = (const uint64_t*)&Bs[kk][ti*8];
            uint64_t b0 = bp[0], b1 = bp[1], b2 = bp[2], b3 = bp[3];
            #pragma unroll
            for (int r = 0; r < 4; ++r) {
                uint64_t ap = pk2(As[kk][tj*4+r]);
                fma2(acc[r][0], ap, b0);
                fma2(acc[r][1], ap, b1);
                fma2(acc[r][2], ap, b2);
                fma2(acc[r][3], ap, b3);
            }
        }
    }
    #pragma unroll
    for (int r = 0; r < 4; ++r) {
        const size_t gi = (size_t)(m0 + tj*4 + r);
        float o[8];
        #pragma unroll
        for (int c = 0; c < 4; ++c) {
            float2 v = up2(acc[r][c]);
            o[c*2+0] = v.x; o[c*2+1] = v.y;
        }
        #pragma unroll
        for (int c = 0; c < 8; ++c) {
            float v = o[c];
            if (bias) v += bias[n0 + ti*8 + c];
            if (act == 1) v = lrelu(v);
            o[c] = v;
        }
        float* orow = C + gi*N + n0 + ti*8;
        *(float4*)orow       = make_float4(o[0],o[1],o[2],o[3]);
        *(float4*)(orow + 4) = make_float4(o[4],o[5],o[6],o[7]);
    }
}

// ---------------- src/dst score kernels ----------------
__global__ void k_srcdst1(const float* __restrict__ a_gat){
    const int row = blockIdx.x;
    const int b = row >> 9, n = row & 511;
    const int tid = threadIdx.x;
    __shared__ float wrow[256];
    wrow[tid] = g_wh1[(size_t)row*256 + tid];
    __syncthreads();
    const int w = tid >> 5, l = tid & 31;
    const int h = w >> 1, half = w & 1;
    float v = wrow[h*64 + l]      * a_gat[h*128 + half*64 + l]
            + wrow[h*64 + 32 + l] * a_gat[h*128 + half*64 + 32 + l];
    #pragma unroll
    for (int o = 16; o; o >>= 1) v += __shfl_down_sync(0xffffffffu, v, o);
    if (l == 0) {
        float* out = half ? g_dst1 : g_src1;
        out[(size_t)(b*4 + h)*512 + n] = v;
    }
}

__global__ void k_srcdst2(const float* __restrict__ a_go){
    const int row = blockIdx.x;
    const int tid = threadIdx.x;
    __shared__ float wrow[128];
    __shared__ float part[4];
    wrow[tid] = g_wh2[(size_t)row*128 + tid];
    __syncthreads();
    const int w = tid >> 5, l = tid & 31;
    const int which = w >> 1, p = w & 1;
    float v = wrow[p*64 + l]      * a_go[which*128 + p*64 + l]
            + wrow[p*64 + 32 + l] * a_go[which*128 + p*64 + 32 + l];
    #pragma unroll
    for (int o = 16; o; o >>= 1) v += __shfl_down_sync(0xffffffffu, v, o);
    if (l == 0) part[w] = v;
    __syncthreads();
    if (tid == 0) g_src2[row] = part[0] + part[1];
    if (tid == 1) g_dst2[row] = part[2] + part[3];
}

// ---------------- fused GAT attention (separable exp) ----------------
// grid: (512/IT, H, B), block 256
template<int F, int IT, int JT>
__global__ void __launch_bounds__(256) k_attn(
    const float* __restrict__ wh, const float* __restrict__ src,
    const float* __restrict__ dst, const int* __restrict__ adj,
    float* __restrict__ out, int WS, int H)
{
    constexpr int CG  = F / 8;        // col groups (8 cols per thread)
    constexpr int RG  = 256 / CG;
    constexpr int R   = IT / RG;      // rows per thread (2)
    constexpr int JTH = 256 / IT;     // threads per i row for att build
    constexpr int AJN = JT / JTH;     // j's per thread per tile

    const int it = blockIdx.x, h = blockIdx.y, b = blockIdx.z;
    const int i0 = it * IT;
    const int tid = threadIdx.x;
    const int whoff = h * 64;

    __shared__ float D[512], P[512], Q[512];
    __shared__ float ssrc[IT], sp[IT], sq[IT], Ssum[IT];
    __shared__ __align__(16) float At[JT][IT+1];
    __shared__ __align__(16) float Bs[JT][F+4];
    __shared__ float pstmp[256];

    const float* dstb = dst + (size_t)(b*H + h) * 512;
    const float* srcb = src + (size_t)(b*H + h) * 512;

    for (int j = tid; j < 512; j += 256) {
        float d = dstb[j];
        D[j] = d; P[j] = __expf(d); Q[j] = __expf(0.2f*d);
    }
    if (tid < IT) {
        float s = srcb[i0 + tid];
        ssrc[tid] = s; sp[tid] = __expf(s); sq[tid] = __expf(0.2f*s);
        Ssum[tid] = 0.f;
    }
    __syncthreads();

    const int ti = tid % CG;
    const int tj = tid / CG;
    uint64_t acc[R][4];
    #pragma unroll
    for (int r = 0; r < R; ++r){ acc[r][0]=0; acc[r][1]=0; acc[r][2]=0; acc[r][3]=0; }

    const int ai  = tid / JTH;
    const int aj0 = (tid % JTH) * AJN;
    const float si  = ssrc[ai];
    const float pie = sp[ai], qie = sq[ai];

    constexpr int NJT = 512 / JT;
    for (int jt = 0; jt < NJT; ++jt) {
        const int j0 = jt * JT;
        __syncthreads();
        // Wh tile
        #pragma unroll
        for (int idx = tid; idx < JT * F / 4; idx += 256) {
            const int j  = idx / (F/4);
            const int f4 = (idx % (F/4)) * 4;
            *(float4*)&Bs[j][f4] =
                *(const float4*)(wh + (size_t)(b*512 + j0 + j)*WS + whoff + f4);
        }
        // unnormalized attention tile (transposed) + partial row sums
        {
            const int4* adjrow = (const int4*)(adj + ((size_t)b*512 + (i0 + ai))*512 + j0 + aj0);
            float ps = 0.f;
            #pragma unroll
            for (int q = 0; q < AJN/4; ++q) {
                int4 a4 = adjrow[q];
                int av[4] = {a4.x, a4.y, a4.z, a4.w};
                #pragma unroll
                for (int t = 0; t < 4; ++t) {
                    const int jj = q*4 + t;
                    float v = 0.f;
                    if (av[t] > 0) {
                        const int j = j0 + aj0 + jj;
                        v = (si + D[j] > 0.f) ? pie * P[j] : qie * Q[j];
                    }
                    At[aj0 + jj][ai] = v;
                    ps += v;
                }
            }
            pstmp[tid] = ps;
        }
        __syncthreads();
        if (tid < IT) {
            float s = 0.f;
            #pragma unroll
            for (int t = 0; t < JTH; ++t) s += pstmp[tid*JTH + t];
            Ssum[tid] += s;
        }
        // acc += At^T @ Bs (packed f32x2)
        #pragma unroll 4
        for (int k = 0; k < JT; ++k) {
            const uint64_t* bp = (const uint64_t*)&Bs[k][ti*8];
            uint64_t b0 = bp[0], b1 = bp[1], b2 = bp[2], b3 = bp[3];
            #pragma unroll
            for (int r = 0; r < R; ++r) {
                uint64_t ap = pk2(At[k][tj*R + r]);
                fma2(acc[r][0], ap, b0);
                fma2(acc[r][1], ap, b1);
                fma2(acc[r][2], ap, b2);
                fma2(acc[r][3], ap, b3);
            }
        }
    }
    __syncthreads();
    #pragma unroll
    for (int r = 0; r < R; ++r) {
        const int i = tj*R + r;
        const float S = Ssum[i];
        const float inv = (S > 0.f) ? 1.f/S : 0.f;
        float o[8];
        #pragma unroll
        for (int c = 0; c < 4; ++c) {
            float2 v = up2(acc[r][c]);
            o[c*2+0] = eluf(v.x * inv);
            o[c*2+1] = eluf(v.y * inv);
        }
        float* orow = out + ((size_t)(b*512) + i0 + i)*WS + whoff + ti*8;
        *(float4*)orow       = make_float4(o[0],o[1],o[2],o[3]);
        *(float4*)(orow + 4) = make_float4(o[4],o[5],o[6],o[7]);
    }
}

// ---------------- CNN ----------------
__global__ void k_conv1(const int* __restrict__ amino, const float* __restrict__ conv_b){
    const int l = blockIdx.x, b = blockIdx.y, f = threadIdx.x;
    float acc = conv_b[0];
    #pragma unroll
    for (int dl = 0; dl < 11; ++dl) {
        int l2 = l + dl - 5;
        if (l2 >= 0 && l2 < 1024) {
            int id = amino[b*1024 + l2];
            acc += g_T[((size_t)id*11 + dl)*128 + f];
        }
    }
    g_cnvA[((size_t)(b*1024) + l)*128 + f] = fmaxf(acc, 0.f);
}

// 11x11 SAME conv + bias + relu on (1024,128); two l-rows packed into f32x2 lanes
__global__ void __launch_bounds__(256) k_conv(
    const float* __restrict__ in, float* __restrict__ out,
    const float* __restrict__ wsrc, const float* __restrict__ bsrc)
{
    __shared__ float tile[26*139];
    __shared__ float ws[121];
    const int lb = blockIdx.x * 16, b = blockIdx.y;
    const int tid = threadIdx.x;
    if (tid < 121) ws[tid] = wsrc[tid];
    for (int idx = tid; idx < 26*138; idx += 256) {
        const int r = idx / 138, c = idx % 138;
        const int gl = lb + r - 5, gf = c - 5;
        float v = 0.f;
        if (gl >= 0 && gl < 1024 && gf >= 0 && gf < 128)
            v = in[((size_t)(b*1024) + gl)*128 + gf];
        tile[r*139 + c] = v;
    }
    __syncthreads();
    const int fg = tid >> 3, lg = tid & 7;
    const int f0 = fg * 4;
    const float bias = bsrc[0];
    uint64_t accp[4];
    {
        uint64_t bp = pk2(bias);
        accp[0]=bp; accp[1]=bp; accp[2]=bp; accp[3]=bp;
    }
    for (int dl = 0; dl < 11; ++dl) {
        const float* w  = ws + dl*11;
        const float* r0 = tile + (lg + dl)*139 + f0;
        const float* r1 = r0 + 8*139;
        uint64_t vp[14];
        #pragma unroll
        for (int j = 0; j < 14; ++j) vp[j] = pk2f(r0[j], r1[j]);
        #pragma unroll
        for (int df = 0; df < 11; ++df) {
            uint64_t wv = pk2(w[df]);
            fma2(accp[0], wv, vp[df+0]);
            fma2(accp[1], wv, vp[df+1]);
            fma2(accp[2], wv, vp[df+2]);
            fma2(accp[3], wv, vp[df+3]);
        }
    }
    float* o0 = out + ((size_t)(b*1024) + lb + lg)*128 + f0;
    float* o1 = o0 + 8*128;
    #pragma unroll
    for (int k = 0; k < 4; ++k) {
        float2 v = up2(accp[k]);
        o0[k] = fmaxf(v.x, 0.f);
        o1[k] = fmaxf(v.y, 0.f);
    }
}

// ---------------- masked mean pooling (two-stage) ----------------
__global__ void k_mean_part(const float* __restrict__ in, const float* __restrict__ mask,
                            int NNd){
    const int ch = blockIdx.x, b = blockIdx.y, f = threadIdx.x;  // 128 thr
    const int rows = NNd / 8;
    const int r0 = ch * rows;
    float s = 0.f, m = 0.f;
    for (int n = r0; n < r0 + rows; ++n) {
        float mk = mask[b*NNd + n];
        m += mk;
        s += mk * in[((size_t)b*NNd + n)*128 + f];
    }
    g_pp[(size_t)(b*8 + ch)*128 + f] = s;
    if (f == 0) g_pm[b*8 + ch] = m;
}

__global__ void k_mean_fin(float* __restrict__ outp){
    const int b = blockIdx.x, f = threadIdx.x;
    float s = 0.f, m = 0.f;
    #pragma unroll
    for (int ch = 0; ch < 8; ++ch) {
        s += g_pp[(size_t)(b*8 + ch)*128 + f];
        m += g_pm[b*8 + ch];
    }
    outp[b*128 + f] = s / m;
}

// ---------------- final predictor ----------------
__global__ void k_final(const float* __restrict__ pred_w, const float* __restrict__ pred_b,
                        float* __restrict__ out){
    __shared__ float red[256];
    const int b = blockIdx.x, c = threadIdx.x;
    float v = (c < 128) ? g_comp[b*128 + c] : g_prot[b*128 + (c - 128)];
    v = v > 0.f ? v : 0.04f*v;
    red[c] = v * pred_w[c];
    __syncthreads();
    for (int s = 128; s > 0; s >>= 1) {
        if (c < s) red[c] += red[c + s];
        __syncthreads();
    }
    if (c == 0) out[b] = red[0] + pred_b[0];
}

// ---------------- launch ----------------
extern "C" void kernel_launch(void* const* d_in, const int* in_sizes, int n_in,
                              void* d_out, int out_size)
{
    const int*   atoms      = (const int*)  d_in[0];
    const float* atoms_mask = (const float*)d_in[1];
    const int*   adj        = (const int*)  d_in[2];
    const int*   amino      = (const int*)  d_in[3];
    const float* amino_mask = (const float*)d_in[4];
    const float* E_atom     = (const float*)d_in[5];
    const float* E_amino    = (const float*)d_in[6];
    const float* W_gat      = (const float*)d_in[7];
    const float* a_gat      = (const float*)d_in[8];
    const float* W_go       = (const float*)d_in[9];
    const float* a_go       = (const float*)d_in[10];
    const float* W_comp_w   = (const float*)d_in[11];
    const float* W_comp_b   = (const float*)d_in[12];
    const float* conv_w     = (const float*)d_in[13];
    const float* conv_b     = (const float*)d_in[14];
    const float* W_att_w    = (const float*)d_in[15];
    const float* W_att_b    = (const float*)d_in[16];
    const float* pred_w     = (const float*)d_in[17];
    const float* pred_b     = (const float*)d_in[18];
    float* out = (float*)d_out;

    float *p_Wcat, *p_WcompT, *p_WattT;
    float *p_av, *p_wh1, *p_multi, *p_wh2, *p_x, *p_atoms_vec, *p_av_att;
    float *p_src1, *p_dst1, *p_src2, *p_dst2, *p_cnvA, *p_cnvB, *p_comp, *p_prot;
    cudaGetSymbolAddress((void**)&p_Wcat,   g_Wcat);
    cudaGetSymbolAddress((void**)&p_WcompT, g_WcompT);
    cudaGetSymbolAddress((void**)&p_WattT,  g_WattT);
    cudaGetSymbolAddress((void**)&p_av,     g_av);
    cudaGetSymbolAddress((void**)&p_wh1,    g_wh1);
    cudaGetSymbolAddress((void**)&p_multi,  g_multi);
    cudaGetSymbolAddress((void**)&p_wh2,    g_wh2);
    cudaGetSymbolAddress((void**)&p_x,      g_x);
    cudaGetSymbolAddress((void**)&p_atoms_vec, g_atoms_vec);
    cudaGetSymbolAddress((void**)&p_av_att, g_av_att);
    cudaGetSymbolAddress((void**)&p_src1,   g_src1);
    cudaGetSymbolAddress((void**)&p_dst1,   g_dst1);
    cudaGetSymbolAddress((void**)&p_src2,   g_src2);
    cudaGetSymbolAddress((void**)&p_dst2,   g_dst2);
    cudaGetSymbolAddress((void**)&p_cnvA,   g_cnvA);
    cudaGetSymbolAddress((void**)&p_cnvB,   g_cnvB);
    cudaGetSymbolAddress((void**)&p_comp,   g_comp);
    cudaGetSymbolAddress((void**)&p_prot,   g_prot);

    // weight prep
    k_pack_wgat<<<128, 256>>>(W_gat);
    k_transp128<<<128, 128>>>(W_comp_w, p_WcompT);
    k_transp128<<<128, 128>>>(W_att_w,  p_WattT);
    k_table<<<dim3(11, 30), 128>>>(conv_w, E_amino);

    // ---- compound branch ----
    k_embed_atoms<<<BB*NN_, 128>>>(atoms, E_atom);
    k_gemm<<<dim3(128, 2), 256>>>(p_av, p_Wcat, nullptr, p_wh1, 8192, 256, 128, 0);
    k_srcdst1<<<BB*NN_, 256>>>(a_gat);
    k_attn<64, 64, 64><<<dim3(8, 4, BB), 256>>>(p_wh1, p_src1, p_dst1, adj, p_multi, 256, 4);
    k_gemm<<<dim3(128, 1), 256>>>(p_multi, W_go, nullptr, p_wh2, 8192, 128, 256, 0);
    k_srcdst2<<<BB*NN_, 128>>>(a_go);
    k_attn<128, 32, 32><<<dim3(16, 1, BB), 256>>>(p_wh2, p_src2, p_dst2, adj, p_x, 128, 1);
    k_gemm<<<dim3(128, 1), 256>>>(p_x, p_WcompT, W_comp_b, p_atoms_vec, 8192, 128, 128, 1);
    k_gemm<<<dim3(128, 1), 256>>>(p_atoms_vec, p_WattT, W_att_b, p_av_att, 8192, 128, 128, 1);
    k_mean_part<<<dim3(8, BB), 128>>>(p_av_att, atoms_mask, NN_);
    k_mean_fin<<<BB, 128>>>(p_comp);

    // ---- protein branch ----
    k_conv1<<<dim3(LL, BB), 128>>>(amino, conv_b);
    k_conv<<<dim3(64, BB), 256>>>(p_cnvA, p_cnvB, conv_w + 121,   conv_b + 1);
    k_conv<<<dim3(64, BB), 256>>>(p_cnvB, p_cnvA, conv_w + 2*121, conv_b + 2);
    k_gemm<<<dim3(256, 1), 256>>>(p_cnvA, p_WattT, W_att_b, p_cnvB, 16384, 128, 128, 1);
    k_mean_part<<<dim3(8, BB), 128>>>(p_cnvB, amino_mask, LL);
    k_mean_fin<<<BB, 128>>>(p_prot);

    // ---- head ----
    k_final<<<BB, 256>>>(pred_w, pred_b, out);
}

// round 5
// speedup vs baseline: 1.7820x; 1.7820x over previous
#include <cuda_runtime.h>
#include <cuda_bf16.h>
#include <math.h>
#include <stdint.h>

// ---------------- constants ----------------
#define BB   16
#define NN_  512
#define LL   1024
#define CD   128
#define GD   64
#define NH   4
#define LAT  128

// ---------------- scratch ----------------
__device__ float g_av       [BB*NN_*CD];
__device__ float g_wh1      [BB*NN_*(GD*NH)];
__device__ float g_multi    [BB*NN_*(GD*NH)];
__device__ float g_wh2      [BB*NN_*CD];
__device__ float g_x        [BB*NN_*CD];
__device__ float g_atoms_vec[BB*NN_*LAT];
__device__ float g_av_att   [BB*NN_*LAT];
__device__ float g_src1[BB*NH*NN_], g_dst1[BB*NH*NN_];
__device__ float g_src2[BB*NN_],    g_dst2[BB*NN_];
__device__ float g_cnvA[BB*LL*CD];
__device__ float g_cnvB[BB*LL*CD];
__device__ float g_T[30*11*CD];
__device__ float g_WcatT[256*128];     // [n=h*64+f][k]
__device__ float g_WgoT [128*256];     // [n][k]
__device__ float g_comp[BB*LAT], g_prot[BB*LAT];
__device__ float g_pp[BB*8*128];
__device__ float g_pm[BB*8];
__device__ uint32_t g_adjmask[BB*NN_*16];

__device__ __forceinline__ float lrelu(float x){ return x > 0.f ? x : 0.2f*x; }
__device__ __forceinline__ float eluf (float x){ return x > 0.f ? x : (__expf(x) - 1.f); }

// ---------------- bf16 split helpers ----------------
__device__ __forceinline__ void split2(float x, float y, uint32_t& hi, uint32_t& lo){
    __nv_bfloat162 h = __floats2bfloat162_rn(x, y);
    float hx = __bfloat162float(h.x), hy = __bfloat162float(h.y);
    __nv_bfloat162 l = __floats2bfloat162_rn(x - hx, y - hy);
    hi = *(uint32_t*)&h; lo = *(uint32_t*)&l;
}
__device__ __forceinline__ void split1(float x, __nv_bfloat16& h, __nv_bfloat16& l){
    h = __float2bfloat16(x);
    l = __float2bfloat16(x - __bfloat162float(h));
}

// mma.sync m16n8k16 bf16 (sm_80+, no tcgen05 needed)
__device__ __forceinline__ void mma16816(float* d, const uint32_t* a, const uint32_t* b){
    asm volatile(
        "mma.sync.aligned.m16n8k16.row.col.f32.bf16.bf16.f32 "
        "{%0,%1,%2,%3},{%4,%5,%6,%7},{%8,%9},{%0,%1,%2,%3};"
        : "+f"(d[0]), "+f"(d[1]), "+f"(d[2]), "+f"(d[3])
        : "r"(a[0]), "r"(a[1]), "r"(a[2]), "r"(a[3]), "r"(b[0]), "r"(b[1]));
}

// ---------------- tiny prep kernels ----------------
__global__ void k_pack_wgatT(const float* __restrict__ W_gat){
    int n = blockIdx.x, k = threadIdx.x;
    int h = n >> 6, f = n & 63;
    g_WcatT[n*128 + k] = W_gat[((h*128) + k)*64 + f];
}
__global__ void k_transp_go(const float* __restrict__ W_go){
    int n = blockIdx.x, k = threadIdx.x;
    g_WgoT[n*256 + k] = W_go[k*128 + n];
}
__global__ void k_table(const float* __restrict__ conv_w, const float* __restrict__ E_amino){
    int dl = blockIdx.x, a = blockIdx.y, f = threadIdx.x;
    float acc = 0.f;
    #pragma unroll
    for (int df = 0; df < 11; ++df) {
        int fi = f + df - 5;
        if (fi >= 0 && fi < 128) acc += conv_w[dl*11 + df] * E_amino[a*128 + fi];
    }
    g_T[(a*11 + dl)*128 + f] = acc;
}
__global__ void k_embed_atoms(const int* __restrict__ atoms, const float* __restrict__ E_atom){
    int row = blockIdx.x, f = threadIdx.x;
    g_av[(size_t)row*128 + f] = E_atom[atoms[row]*128 + f];
}
__global__ void k_packadj(const int* __restrict__ adj){
    int t = blockIdx.x*256 + threadIdx.x;
    const int* base = adj + (size_t)t*32;
    uint32_t m = 0;
    #pragma unroll
    for (int k = 0; k < 32; ++k) m |= (base[k] > 0 ? 1u : 0u) << k;
    g_adjmask[t] = m;
}

// ---------------- bf16-split tensor GEMM: C = act(A @ BT^T + bias) ----------------
// A[M,K] f32 row-major, BT[N,K] f32 row-major. Block tile 64x128, 8 warps (32x32).
// smem tiles bf16 hi/lo, pitch 72 bf16 (=36 words) -> conflict-free frag loads.
template<int ACT>
__global__ void __launch_bounds__(256) k_mm(
    const float* __restrict__ A, const float* __restrict__ BT,
    const float* __restrict__ bias, float* __restrict__ C,
    int M, int N, int K)
{
    extern __shared__ char sm[];
    uint32_t* Ah = (uint32_t*)(sm);             // 64*36 words  = 9216 B
    uint32_t* Al = (uint32_t*)(sm + 9216);
    uint32_t* Bh = (uint32_t*)(sm + 18432);     // 128*36 words = 18432 B
    uint32_t* Bl = (uint32_t*)(sm + 36864);     // total 55296

    const int m0 = blockIdx.x*64, n0 = blockIdx.y*128;
    const int tid = threadIdx.x, w = tid >> 5, lane = tid & 31;
    const int wm = w & 1, wn = w >> 1;          // 2 x 4 warps
    const int r4 = lane >> 2, cl = lane & 3;

    float acc[2][4][4];
    #pragma unroll
    for (int i = 0; i < 2; ++i)
        #pragma unroll
        for (int j = 0; j < 4; ++j)
            #pragma unroll
            for (int q = 0; q < 4; ++q) acc[i][j][q] = 0.f;

    for (int k0 = 0; k0 < K; k0 += 64) {
        __syncthreads();
        // A chunk: 64 rows x 64 k
        #pragma unroll
        for (int s = tid; s < 1024; s += 256) {
            int r = s >> 4, q = s & 15;
            float4 v = *(const float4*)&A[(size_t)(m0+r)*K + k0 + q*4];
            uint32_t h0,l0,h1,l1;
            split2(v.x, v.y, h0, l0); split2(v.z, v.w, h1, l1);
            int off = r*36 + q*2;
            Ah[off] = h0; Ah[off+1] = h1;
            Al[off] = l0; Al[off+1] = l1;
        }
        // B chunk: 128 rows x 64 k
        #pragma unroll
        for (int s = tid; s < 2048; s += 256) {
            int r = s >> 4, q = s & 15;
            float4 v = *(const float4*)&BT[(size_t)(n0+r)*K + k0 + q*4];
            uint32_t h0,l0,h1,l1;
            split2(v.x, v.y, h0, l0); split2(v.z, v.w, h1, l1);
            int off = r*36 + q*2;
            Bh[off] = h0; Bh[off+1] = h1;
            Bl[off] = l0; Bl[off+1] = l1;
        }
        __syncthreads();
        #pragma unroll
        for (int kk = 0; kk < 4; ++kk) {
            const int kw = kk*8;
            uint32_t ah[2][4], al[2][4];
            #pragma unroll
            for (int fm = 0; fm < 2; ++fm) {
                int base = (wm*32 + fm*16 + r4)*36 + kw + cl;
                ah[fm][0]=Ah[base];     ah[fm][1]=Ah[base+288];
                ah[fm][2]=Ah[base+4];   ah[fm][3]=Ah[base+292];
                al[fm][0]=Al[base];     al[fm][1]=Al[base+288];
                al[fm][2]=Al[base+4];   al[fm][3]=Al[base+292];
            }
            uint32_t bh[4][2], bl[4][2];
            #pragma unroll
            for (int fn = 0; fn < 4; ++fn) {
                int base = (wn*32 + fn*8 + r4)*36 + kw + cl;
                bh[fn][0]=Bh[base]; bh[fn][1]=Bh[base+4];
                bl[fn][0]=Bl[base]; bl[fn][1]=Bl[base+4];
            }
            #pragma unroll
            for (int fm = 0; fm < 2; ++fm)
                #pragma unroll
                for (int fn = 0; fn < 4; ++fn) {
                    mma16816(acc[fm][fn], ah[fm], bh[fn]);
                    mma16816(acc[fm][fn], ah[fm], bl[fn]);
                    mma16816(acc[fm][fn], al[fm], bh[fn]);
                }
        }
    }
    // epilogue
    #pragma unroll
    for (int fm = 0; fm < 2; ++fm) {
        #pragma unroll
        for (int fn = 0; fn < 4; ++fn) {
            int row = m0 + wm*32 + fm*16 + r4;
            int col = n0 + wn*32 + fn*8 + 2*cl;
            float b0 = 0.f, b1 = 0.f;
            if (bias) { b0 = bias[col]; b1 = bias[col+1]; }
            float v0 = acc[fm][fn][0] + b0, v1 = acc[fm][fn][1] + b1;
            float v2 = acc[fm][fn][2] + b0, v3 = acc[fm][fn][3] + b1;
            if (ACT) { v0=lrelu(v0); v1=lrelu(v1); v2=lrelu(v2); v3=lrelu(v3); }
            *(float2*)&C[(size_t)row*N + col]     = make_float2(v0, v1);
            *(float2*)&C[(size_t)(row+8)*N + col] = make_float2(v2, v3);
        }
    }
}

// ---------------- tensor-core GAT attention (separable exp + bf16 split) ----------------
// grid (4, H, B), block 256. out[i, h*64..h*64+F) = elu(softmax(masked)@Wh)
template<int F>
__global__ void __launch_bounds__(256) k_attn(
    const float* __restrict__ wh, const float* __restrict__ src,
    const float* __restrict__ dst, const uint32_t* __restrict__ adjmask,
    float* __restrict__ out, int WS, int H)
{
    extern __shared__ char sm[];
    float* Df  = (float*)(sm);            // 2048
    float* Pf  = (float*)(sm + 2048);
    float* Qf  = (float*)(sm + 4096);
    float* sS  = (float*)(sm + 6144);     // 512
    float* sP  = (float*)(sm + 6656);
    float* sQ  = (float*)(sm + 7168);
    float* Sum = (float*)(sm + 7680);     // 512
    float* pst = (float*)(sm + 8192);     // 1024
    uint32_t* msk = (uint32_t*)(sm + 9216);   // 8192
    uint32_t* Ath = (uint32_t*)(sm + 17408);  // 128*18 words = 9216 B
    uint32_t* Atl = (uint32_t*)(sm + 26624);
    uint32_t* Bh  = (uint32_t*)(sm + 35840);  // F*18 words
    uint32_t* Bl  = (uint32_t*)(sm + 35840 + F*72);

    const int it = blockIdx.x, h = blockIdx.y, b = blockIdx.z;
    const int i0 = it*128;
    const int tid = threadIdx.x, w = tid >> 5, lane = tid & 31;
    const int r4 = lane >> 2, cl = lane & 3;
    const int whoff = h*64;

    constexpr int WM  = (F == 64) ? 32 : 64;   // warp m-tile
    constexpr int NWM = 128 / WM;              // warps in m dir
    constexpr int FM  = WM / 16;               // m frags per warp
    const int wm = w % NWM, wn = w / NWM;

    const float* dstb = dst + (size_t)(b*H + h)*512;
    const float* srcb = src + (size_t)(b*H + h)*512;
    for (int j = tid; j < 512; j += 256) {
        float d = dstb[j];
        Df[j] = d; Pf[j] = __expf(d); Qf[j] = __expf(0.2f*d);
    }
    if (tid < 128) {
        float s = srcb[i0 + tid];
        sS[tid] = s; sP[tid] = __expf(s); sQ[tid] = __expf(0.2f*s);
    }
    {
        const uint32_t* mb = adjmask + ((size_t)(b*512) + i0)*16;
        for (int s = tid; s < 2048; s += 256) msk[s] = mb[s];
    }

    float acc[FM][4][4];
    #pragma unroll
    for (int i = 0; i < FM; ++i)
        #pragma unroll
        for (int j = 0; j < 4; ++j)
            #pragma unroll
            for (int q = 0; q < 4; ++q) acc[i][j][q] = 0.f;

    const int ai = tid >> 1, half = tid & 1;
    __syncthreads();
    const float si = sS[ai], pie = sP[ai], qie = sQ[ai];
    float ps = 0.f;

    for (int c = 0; c < 16; ++c) {
        const int j0 = c*32;
        if (c) __syncthreads();
        // --- A tile build (128 x 32) hi/lo ---
        {
            uint32_t mw = msk[ai*16 + c];
            #pragma unroll
            for (int jj = 0; jj < 8; ++jj) {
                int jl0 = half*16 + jj*2, jl1 = jl0 + 1;
                float v0 = 0.f, v1 = 0.f;
                if ((mw >> jl0) & 1u) {
                    int j = j0 + jl0;
                    v0 = (si + Df[j] > 0.f) ? pie*Pf[j] : qie*Qf[j];
                }
                if ((mw >> jl1) & 1u) {
                    int j = j0 + jl1;
                    v1 = (si + Df[j] > 0.f) ? pie*Pf[j] : qie*Qf[j];
                }
                ps += v0 + v1;
                uint32_t hw, lw; split2(v0, v1, hw, lw);
                int off = ai*18 + half*8 + jj;
                Ath[off] = hw; Atl[off] = lw;
            }
        }
        // --- B tile build: WhT [F x 32] hi/lo via transposed stores ---
        __nv_bfloat16* Bhb = (__nv_bfloat16*)Bh;
        __nv_bfloat16* Blb = (__nv_bfloat16*)Bl;
        if (F == 64) {
            const int f = tid & 63, jg = tid >> 6;
            #pragma unroll
            for (int jj = 0; jj < 8; ++jj) {
                int jl = jg*8 + jj;
                float v = wh[(size_t)(b*512 + j0 + jl)*WS + whoff + f];
                __nv_bfloat16 hv, lv; split1(v, hv, lv);
                Bhb[f*36 + jl] = hv; Blb[f*36 + jl] = lv;
            }
        } else {
            const int f = tid & 127, jg = tid >> 7;
            #pragma unroll
            for (int jj = 0; jj < 16; ++jj) {
                int jl = jg*16 + jj;
                float v = wh[(size_t)(b*512 + j0 + jl)*WS + whoff + f];
                __nv_bfloat16 hv, lv; split1(v, hv, lv);
                Bhb[f*36 + jl] = hv; Blb[f*36 + jl] = lv;
            }
        }
        __syncthreads();
        // --- MMA: 2 k-steps of 16 ---
        #pragma unroll
        for (int kk = 0; kk < 2; ++kk) {
            const int kw = kk*8;
            uint32_t ah[FM][4], al[FM][4];
            #pragma unroll
            for (int fm = 0; fm < FM; ++fm) {
                int base = (wm*WM + fm*16 + r4)*18 + kw + cl;
                ah[fm][0]=Ath[base];     ah[fm][1]=Ath[base+144];
                ah[fm][2]=Ath[base+4];   ah[fm][3]=Ath[base+148];
                al[fm][0]=Atl[base];     al[fm][1]=Atl[base+144];
                al[fm][2]=Atl[base+4];   al[fm][3]=Atl[base+148];
            }
            uint32_t bh[4][2], bl[4][2];
            #pragma unroll
            for (int fn = 0; fn < 4; ++fn) {
                int base = (wn*32 + fn*8 + r4)*18 + kw + cl;
                bh[fn][0]=Bh[base]; bh[fn][1]=Bh[base+4];
                bl[fn][0]=Bl[base]; bl[fn][1]=Bl[base+4];
            }
            #pragma unroll
            for (int fm = 0; fm < FM; ++fm)
                #pragma unroll
                for (int fn = 0; fn < 4; ++fn) {
                    mma16816(acc[fm][fn], ah[fm], bh[fn]);
                    mma16816(acc[fm][fn], ah[fm], bl[fn]);
                    mma16816(acc[fm][fn], al[fm], bh[fn]);
                }
        }
    }
    pst[tid] = ps;
    __syncthreads();
    if (tid < 128) Sum[tid] = pst[2*tid] + pst[2*tid+1];
    __syncthreads();
    // --- epilogue: normalize + elu ---
    #pragma unroll
    for (int fm = 0; fm < FM; ++fm) {
        int rl = wm*WM + fm*16 + r4;
        float S0 = Sum[rl],   i0v = (S0 > 0.f) ? 1.f/S0 : 0.f;
        float S1 = Sum[rl+8], i1v = (S1 > 0.f) ? 1.f/S1 : 0.f;
        #pragma unroll
        for (int fn = 0; fn < 4; ++fn) {
            int col = whoff + wn*32 + fn*8 + 2*cl;
            float v0 = eluf(acc[fm][fn][0] * i0v);
            float v1 = eluf(acc[fm][fn][1] * i0v);
            float v2 = eluf(acc[fm][fn][2] * i1v);
            float v3 = eluf(acc[fm][fn][3] * i1v);
            *(float2*)&out[(size_t)(b*512 + i0 + rl)*WS + col]     = make_float2(v0, v1);
            *(float2*)&out[(size_t)(b*512 + i0 + rl + 8)*WS + col] = make_float2(v2, v3);
        }
    }
}

// ---------------- src/dst score kernels ----------------
__global__ void k_srcdst1(const float* __restrict__ a_gat){
    const int row = blockIdx.x;
    const int b = row >> 9, n = row & 511;
    const int tid = threadIdx.x;
    __shared__ float wrow[256];
    wrow[tid] = g_wh1[(size_t)row*256 + tid];
    __syncthreads();
    const int w = tid >> 5, l = tid & 31;
    const int h = w >> 1, half = w & 1;
    float v = wrow[h*64 + l]      * a_gat[h*128 + half*64 + l]
            + wrow[h*64 + 32 + l] * a_gat[h*128 + half*64 + 32 + l];
    #pragma unroll
    for (int o = 16; o; o >>= 1) v += __shfl_down_sync(0xffffffffu, v, o);
    if (l == 0) {
        float* outp = half ? g_dst1 : g_src1;
        outp[(size_t)(b*4 + h)*512 + n] = v;
    }
}
__global__ void k_srcdst2(const float* __restrict__ a_go){
    const int row = blockIdx.x;
    const int tid = threadIdx.x;
    __shared__ float wrow[128];
    __shared__ float part[4];
    wrow[tid] = g_wh2[(size_t)row*128 + tid];
    __syncthreads();
    const int w = tid >> 5, l = tid & 31;
    const int which = w >> 1, p = w & 1;
    float v = wrow[p*64 + l]      * a_go[which*128 + p*64 + l]
            + wrow[p*64 + 32 + l] * a_go[which*128 + p*64 + 32 + l];
    #pragma unroll
    for (int o = 16; o; o >>= 1) v += __shfl_down_sync(0xffffffffu, v, o);
    if (l == 0) part[w] = v;
    __syncthreads();
    if (tid == 0) g_src2[row] = part[0] + part[1];
    if (tid == 1) g_dst2[row] = part[2] + part[3];
}

// ---------------- CNN ----------------
__global__ void k_conv1(const int* __restrict__ amino, const float* __restrict__ conv_b){
    const int l = blockIdx.x, b = blockIdx.y, f = threadIdx.x;
    float acc = conv_b[0];
    #pragma unroll
    for (int dl = 0; dl < 11; ++dl) {
        int l2 = l + dl - 5;
        if (l2 >= 0 && l2 < 1024) {
            int id = amino[b*1024 + l2];
            acc += g_T[((size_t)id*11 + dl)*128 + f];
        }
    }
    g_cnvA[((size_t)(b*1024) + l)*128 + f] = fmaxf(acc, 0.f);
}
__global__ void __launch_bounds__(256) k_conv(
    const float* __restrict__ in, float* __restrict__ out,
    const float* __restrict__ wsrc, const float* __restrict__ bsrc)
{
    __shared__ float tile[26*139];
    __shared__ float ws[121];
    const int lb = blockIdx.x * 16, b = blockIdx.y;
    const int tid = threadIdx.x;
    if (tid < 121) ws[tid] = wsrc[tid];
    for (int idx = tid; idx < 26*138; idx += 256) {
        const int r = idx / 138, c = idx % 138;
        const int gl = lb + r - 5, gf = c - 5;
        float v = 0.f;
        if (gl >= 0 && gl < 1024 && gf >= 0 && gf < 128)
            v = in[((size_t)(b*1024) + gl)*128 + gf];
        tile[r*139 + c] = v;
    }
    __syncthreads();
    const int fg = tid >> 3, lg = tid & 7;
    const int f0 = fg * 4;
    const float bias = bsrc[0];
    float acc0[4] = {bias,bias,bias,bias};
    float acc1[4] = {bias,bias,bias,bias};
    for (int dl = 0; dl < 11; ++dl) {
        const float* w  = ws + dl*11;
        const float* r0 = tile + (lg + dl)*139 + f0;
        const float* r1 = r0 + 8*139;
        float v0[14], v1[14];
        #pragma unroll
        for (int j = 0; j < 14; ++j) { v0[j] = r0[j]; v1[j] = r1[j]; }
        #pragma unroll
        for (int df = 0; df < 11; ++df) {
            const float wv = w[df];
            #pragma unroll
            for (int k = 0; k < 4; ++k) {
                acc0[k] += wv * v0[df+k];
                acc1[k] += wv * v1[df+k];
            }
        }
    }
    float* o0 = out + ((size_t)(b*1024) + lb + lg)*128 + f0;
    float* o1 = o0 + 8*128;
    #pragma unroll
    for (int k = 0; k < 4; ++k) {
        o0[k] = fmaxf(acc0[k], 0.f);
        o1[k] = fmaxf(acc1[k], 0.f);
    }
}

// ---------------- masked mean pooling ----------------
__global__ void k_mean_part(const float* __restrict__ in, const float* __restrict__ mask,
                            int NNd){
    const int ch = blockIdx.x, b = blockIdx.y, f = threadIdx.x;
    const int rows = NNd / 8;
    const int r0 = ch * rows;
    float s = 0.f, m = 0.f;
    for (int n = r0; n < r0 + rows; ++n) {
        float mk = mask[b*NNd + n];
        m += mk;
        s += mk * in[((size_t)b*NNd + n)*128 + f];
    }
    g_pp[(size_t)(b*8 + ch)*128 + f] = s;
    if (f == 0) g_pm[b*8 + ch] = m;
}
__global__ void k_mean_fin(float* __restrict__ outp){
    const int b = blockIdx.x, f = threadIdx.x;
    float s = 0.f, m = 0.f;
    #pragma unroll
    for (int ch = 0; ch < 8; ++ch) {
        s += g_pp[(size_t)(b*8 + ch)*128 + f];
        m += g_pm[b*8 + ch];
    }
    outp[b*128 + f] = s / m;
}

// ---------------- final predictor ----------------
__global__ void k_final(const float* __restrict__ pred_w, const float* __restrict__ pred_b,
                        float* __restrict__ out){
    __shared__ float red[256];
    const int b = blockIdx.x, c = threadIdx.x;
    float v = (c < 128) ? g_comp[b*128 + c] : g_prot[b*128 + (c - 128)];
    v = v > 0.f ? v : 0.04f*v;
    red[c] = v * pred_w[c];
    __syncthreads();
    for (int s = 128; s > 0; s >>= 1) {
        if (c < s) red[c] += red[c + s];
        __syncthreads();
    }
    if (c == 0) out[b] = red[0] + pred_b[0];
}

// ---------------- launch ----------------
extern "C" void kernel_launch(void* const* d_in, const int* in_sizes, int n_in,
                              void* d_out, int out_size)
{
    const int*   atoms      = (const int*)  d_in[0];
    const float* atoms_mask = (const float*)d_in[1];
    const int*   adj        = (const int*)  d_in[2];
    const int*   amino      = (const int*)  d_in[3];
    const float* amino_mask = (const float*)d_in[4];
    const float* E_atom     = (const float*)d_in[5];
    const float* E_amino    = (const float*)d_in[6];
    const float* W_gat      = (const float*)d_in[7];
    const float* a_gat      = (const float*)d_in[8];
    const float* W_go       = (const float*)d_in[9];
    const float* a_go       = (const float*)d_in[10];
    const float* W_comp_w   = (const float*)d_in[11];
    const float* W_comp_b   = (const float*)d_in[12];
    const float* conv_w     = (const float*)d_in[13];
    const float* conv_b     = (const float*)d_in[14];
    const float* W_att_w    = (const float*)d_in[15];
    const float* W_att_b    = (const float*)d_in[16];
    const float* pred_w     = (const float*)d_in[17];
    const float* pred_b     = (const float*)d_in[18];
    float* out = (float*)d_out;

    float *p_WcatT, *p_WgoT;
    float *p_av, *p_wh1, *p_multi, *p_wh2, *p_x, *p_atoms_vec, *p_av_att;
    float *p_src1, *p_dst1, *p_src2, *p_dst2, *p_cnvA, *p_cnvB, *p_comp, *p_prot;
    uint32_t* p_adjm;
    cudaGetSymbolAddress((void**)&p_WcatT, g_WcatT);
    cudaGetSymbolAddress((void**)&p_WgoT,  g_WgoT);
    cudaGetSymbolAddress((void**)&p_av,    g_av);
    cudaGetSymbolAddress((void**)&p_wh1,   g_wh1);
    cudaGetSymbolAddress((void**)&p_multi, g_multi);
    cudaGetSymbolAddress((void**)&p_wh2,   g_wh2);
    cudaGetSymbolAddress((void**)&p_x,     g_x);
    cudaGetSymbolAddress((void**)&p_atoms_vec, g_atoms_vec);
    cudaGetSymbolAddress((void**)&p_av_att, g_av_att);
    cudaGetSymbolAddress((void**)&p_src1,  g_src1);
    cudaGetSymbolAddress((void**)&p_dst1,  g_dst1);
    cudaGetSymbolAddress((void**)&p_src2,  g_src2);
    cudaGetSymbolAddress((void**)&p_dst2,  g_dst2);
    cudaGetSymbolAddress((void**)&p_cnvA,  g_cnvA);
    cudaGetSymbolAddress((void**)&p_cnvB,  g_cnvB);
    cudaGetSymbolAddress((void**)&p_comp,  g_comp);
    cudaGetSymbolAddress((void**)&p_prot,  g_prot);
    cudaGetSymbolAddress((void**)&p_adjm,  g_adjmask);

    const int SM_MM    = 55296;
    const int SM_AT64  = 35840 + 64*72*2;    // 45056
    const int SM_AT128 = 35840 + 128*72*2;   // 54272
    cudaFuncSetAttribute(k_mm<0>,    cudaFuncAttributeMaxDynamicSharedMemorySize, SM_MM);
    cudaFuncSetAttribute(k_mm<1>,    cudaFuncAttributeMaxDynamicSharedMemorySize, SM_MM);
    cudaFuncSetAttribute(k_attn<64>, cudaFuncAttributeMaxDynamicSharedMemorySize, SM_AT64);
    cudaFuncSetAttribute(k_attn<128>,cudaFuncAttributeMaxDynamicSharedMemorySize, SM_AT128);

    // weight prep
    k_pack_wgatT<<<256, 128>>>(W_gat);
    k_transp_go<<<128, 256>>>(W_go);
    k_table<<<dim3(11, 30), 128>>>(conv_w, E_amino);
    k_packadj<<<512, 256>>>(adj);

    // ---- compound branch ----
    k_embed_atoms<<<BB*NN_, 128>>>(atoms, E_atom);
    k_mm<0><<<dim3(128, 2), 256, SM_MM>>>(p_av, p_WcatT, nullptr, p_wh1, 8192, 256, 128);
    k_srcdst1<<<BB*NN_, 256>>>(a_gat);
    k_attn<64><<<dim3(4, 4, BB), 256, SM_AT64>>>(p_wh1, p_src1, p_dst1, p_adjm, p_multi, 256, 4);
    k_mm<0><<<dim3(128, 1), 256, SM_MM>>>(p_multi, p_WgoT, nullptr, p_wh2, 8192, 128, 256);
    k_srcdst2<<<BB*NN_, 128>>>(a_go);
    k_attn<128><<<dim3(4, 1, BB), 256, SM_AT128>>>(p_wh2, p_src2, p_dst2, p_adjm, p_x, 128, 1);
    k_mm<1><<<dim3(128, 1), 256, SM_MM>>>(p_x, W_comp_w, W_comp_b, p_atoms_vec, 8192, 128, 128);
    k_mm<1><<<dim3(128, 1), 256, SM_MM>>>(p_atoms_vec, W_att_w, W_att_b, p_av_att, 8192, 128, 128);
    k_mean_part<<<dim3(8, BB), 128>>>(p_av_att, atoms_mask, NN_);
    k_mean_fin<<<BB, 128>>>(p_comp);

    // ---- protein branch ----
    k_conv1<<<dim3(LL, BB), 128>>>(amino, conv_b);
    k_conv<<<dim3(64, BB), 256>>>(p_cnvA, p_cnvB, conv_w + 121,   conv_b + 1);
    k_conv<<<dim3(64, BB), 256>>>(p_cnvB, p_cnvA, conv_w + 2*121, conv_b + 2);
    k_mm<1><<<dim3(256, 1), 256, SM_MM>>>(p_cnvA, W_att_w, W_att_b, p_cnvB, 16384, 128, 128);
    k_mean_part<<<dim3(8, BB), 128>>>(p_cnvB, amino_mask, LL);
    k_mean_fin<<<BB, 128>>>(p_prot);

    // ---- head ----
    k_final<<<BB, 256>>>(pred_w, pred_b, out);
}

// round 6
// speedup vs baseline: 1.9138x; 1.0740x over previous
#include <cuda_runtime.h>
#include <cuda_bf16.h>
#include <math.h>
#include <stdint.h>

// ---------------- constants ----------------
#define BB   16
#define NN_  512
#define LL   1024
#define CD   128
#define GD   64
#define NH   4
#define LAT  128

// ---------------- scratch ----------------
__device__ float g_av       [BB*NN_*CD];
__device__ float g_wh1      [BB*NN_*(GD*NH)];
__device__ float g_multi    [BB*NN_*(GD*NH)];
__device__ float g_wh2      [BB*NN_*CD];
__device__ float g_x        [BB*NN_*CD];
__device__ float g_atoms_vec[BB*NN_*LAT];
__device__ float g_av_att   [BB*NN_*LAT];
__device__ float g_src1[BB*NH*NN_], g_dst1[BB*NH*NN_];
__device__ float g_src2[BB*NN_],    g_dst2[BB*NN_];
__device__ float g_cnvA[BB*LL*CD];
__device__ float g_cnvB[BB*LL*CD];
__device__ float g_T[30*11*CD];
__device__ float g_WcatT[256*128];     // [n=h*64+f][k]
__device__ float g_WgoT [128*256];     // [n][k]
__device__ float g_comp[BB*LAT], g_prot[BB*LAT];
__device__ float g_pp[BB*8*128];
__device__ float g_pm[BB*8];
__device__ uint32_t g_adjmask[BB*NN_*16];

__device__ __forceinline__ float lrelu(float x){ return x > 0.f ? x : 0.2f*x; }
__device__ __forceinline__ float eluf (float x){ return x > 0.f ? x : (__expf(x) - 1.f); }

// ---------------- f32x2 packed helpers (conv only) ----------------
__device__ __forceinline__ uint64_t pk2(float x){
    uint32_t xi = __float_as_uint(x);
    uint64_t r; asm("mov.b64 %0, {%1, %1};" : "=l"(r) : "r"(xi)); return r;
}
__device__ __forceinline__ uint64_t pk2f(float x, float y){
    uint32_t xi = __float_as_uint(x), yi = __float_as_uint(y);
    uint64_t r; asm("mov.b64 %0, {%1, %2};" : "=l"(r) : "r"(xi), "r"(yi)); return r;
}
__device__ __forceinline__ void fma2(uint64_t& d, uint64_t a, uint64_t b){
    asm("fma.rn.f32x2 %0, %1, %2, %0;" : "+l"(d) : "l"(a), "l"(b));
}
__device__ __forceinline__ float2 up2(uint64_t v){
    uint32_t lo, hi; asm("mov.b64 {%0, %1}, %2;" : "=r"(lo), "=r"(hi) : "l"(v));
    return make_float2(__uint_as_float(lo), __uint_as_float(hi));
}

// ---------------- bf16 split helpers ----------------
__device__ __forceinline__ void split2(float x, float y, uint32_t& hi, uint32_t& lo){
    __nv_bfloat162 h = __floats2bfloat162_rn(x, y);
    float hx = __bfloat162float(h.x), hy = __bfloat162float(h.y);
    __nv_bfloat162 l = __floats2bfloat162_rn(x - hx, y - hy);
    hi = *(uint32_t*)&h; lo = *(uint32_t*)&l;
}
__device__ __forceinline__ void split1(float x, __nv_bfloat16& h, __nv_bfloat16& l){
    h = __float2bfloat16(x);
    l = __float2bfloat16(x - __bfloat162float(h));
}

// mma.sync m16n8k16 bf16 (sm_80+)
__device__ __forceinline__ void mma16816(float* d, const uint32_t* a, const uint32_t* b){
    asm volatile(
        "mma.sync.aligned.m16n8k16.row.col.f32.bf16.bf16.f32 "
        "{%0,%1,%2,%3},{%4,%5,%6,%7},{%8,%9},{%0,%1,%2,%3};"
        : "+f"(d[0]), "+f"(d[1]), "+f"(d[2]), "+f"(d[3])
        : "r"(a[0]), "r"(a[1]), "r"(a[2]), "r"(a[3]), "r"(b[0]), "r"(b[1]));
}

// ---------------- fused prep kernel (packadj + weight packs + table + embed) ----------------
// block ranges: [0,16384) packadj | [16384,16512) wgatT | [16512,16640) goT
//               [16640,16805) table | [16805,20901) embed
__global__ void __launch_bounds__(256) k_prep(
    const int* __restrict__ adj, const float* __restrict__ W_gat,
    const float* __restrict__ W_go, const float* __restrict__ conv_w,
    const float* __restrict__ E_amino, const int* __restrict__ atoms,
    const float* __restrict__ E_atom)
{
    const int bid = blockIdx.x, tid = threadIdx.x;
    if (bid < 16384) {
        int t = bid*256 + tid;                 // one int per thread
        uint32_t bal = __ballot_sync(0xffffffffu, adj[t] > 0);
        if ((t & 31) == 0) g_adjmask[t >> 5] = bal;
    } else if (bid < 16512) {
        int idx = (bid - 16384)*256 + tid;     // 32768
        int n = idx >> 7, k = idx & 127;
        int h = n >> 6, f = n & 63;
        g_WcatT[n*128 + k] = W_gat[((h*128) + k)*64 + f];
    } else if (bid < 16640) {
        int idx = (bid - 16512)*256 + tid;     // 32768
        int n = idx >> 8, k = idx & 255;
        g_WgoT[n*256 + k] = W_go[k*128 + n];
    } else if (bid < 16805) {
        int idx = (bid - 16640)*256 + tid;     // 42240 valid
        if (idx < 42240) {
            int f = idx & 127, rest = idx >> 7;
            int dl = rest % 11, a = rest / 11;
            float acc = 0.f;
            #pragma unroll
            for (int df = 0; df < 11; ++df) {
                int fi = f + df - 5;
                if (fi >= 0 && fi < 128) acc += conv_w[dl*11 + df] * E_amino[a*128 + fi];
            }
            g_T[(a*11 + dl)*128 + f] = acc;
        }
    } else {
        int idx = (bid - 16805)*256 + tid;     // 1048576
        int row = idx >> 7, f = idx & 127;
        g_av[(size_t)row*128 + f] = E_atom[atoms[row]*128 + f];
    }
}

// ---------------- bf16-split tensor GEMM: C = act(A @ BT^T + bias) ----------------
template<int ACT>
__global__ void __launch_bounds__(256) k_mm(
    const float* __restrict__ A, const float* __restrict__ BT,
    const float* __restrict__ bias, float* __restrict__ C,
    int M, int N, int K)
{
    extern __shared__ char sm[];
    uint32_t* Ah = (uint32_t*)(sm);
    uint32_t* Al = (uint32_t*)(sm + 9216);
    uint32_t* Bh = (uint32_t*)(sm + 18432);
    uint32_t* Bl = (uint32_t*)(sm + 36864);

    const int m0 = blockIdx.x*64, n0 = blockIdx.y*128;
    const int tid = threadIdx.x, w = tid >> 5, lane = tid & 31;
    const int wm = w & 1, wn = w >> 1;
    const int r4 = lane >> 2, cl = lane & 3;

    float acc[2][4][4];
    #pragma unroll
    for (int i = 0; i < 2; ++i)
        #pragma unroll
        for (int j = 0; j < 4; ++j)
            #pragma unroll
            for (int q = 0; q < 4; ++q) acc[i][j][q] = 0.f;

    for (int k0 = 0; k0 < K; k0 += 64) {
        __syncthreads();
        #pragma unroll
        for (int s = tid; s < 1024; s += 256) {
            int r = s >> 4, q = s & 15;
            float4 v = *(const float4*)&A[(size_t)(m0+r)*K + k0 + q*4];
            uint32_t h0,l0,h1,l1;
            split2(v.x, v.y, h0, l0); split2(v.z, v.w, h1, l1);
            int off = r*36 + q*2;
            Ah[off] = h0; Ah[off+1] = h1;
            Al[off] = l0; Al[off+1] = l1;
        }
        #pragma unroll
        for (int s = tid; s < 2048; s += 256) {
            int r = s >> 4, q = s & 15;
            float4 v = *(const float4*)&BT[(size_t)(n0+r)*K + k0 + q*4];
            uint32_t h0,l0,h1,l1;
            split2(v.x, v.y, h0, l0); split2(v.z, v.w, h1, l1);
            int off = r*36 + q*2;
            Bh[off] = h0; Bh[off+1] = h1;
            Bl[off] = l0; Bl[off+1] = l1;
        }
        __syncthreads();
        #pragma unroll
        for (int kk = 0; kk < 4; ++kk) {
            const int kw = kk*8;
            uint32_t ah[2][4], al[2][4];
            #pragma unroll
            for (int fm = 0; fm < 2; ++fm) {
                int base = (wm*32 + fm*16 + r4)*36 + kw + cl;
                ah[fm][0]=Ah[base];     ah[fm][1]=Ah[base+288];
                ah[fm][2]=Ah[base+4];   ah[fm][3]=Ah[base+292];
                al[fm][0]=Al[base];     al[fm][1]=Al[base+288];
                al[fm][2]=Al[base+4];   al[fm][3]=Al[base+292];
            }
            uint32_t bh[4][2], bl[4][2];
            #pragma unroll
            for (int fn = 0; fn < 4; ++fn) {
                int base = (wn*32 + fn*8 + r4)*36 + kw + cl;
                bh[fn][0]=Bh[base]; bh[fn][1]=Bh[base+4];
                bl[fn][0]=Bl[base]; bl[fn][1]=Bl[base+4];
            }
            #pragma unroll
            for (int fm = 0; fm < 2; ++fm)
                #pragma unroll
                for (int fn = 0; fn < 4; ++fn) {
                    mma16816(acc[fm][fn], ah[fm], bh[fn]);
                    mma16816(acc[fm][fn], ah[fm], bl[fn]);
                    mma16816(acc[fm][fn], al[fm], bh[fn]);
                }
        }
    }
    #pragma unroll
    for (int fm = 0; fm < 2; ++fm) {
        #pragma unroll
        for (int fn = 0; fn < 4; ++fn) {
            int row = m0 + wm*32 + fm*16 + r4;
            int col = n0 + wn*32 + fn*8 + 2*cl;
            float b0 = 0.f, b1 = 0.f;
            if (bias) { b0 = bias[col]; b1 = bias[col+1]; }
            float v0 = acc[fm][fn][0] + b0, v1 = acc[fm][fn][1] + b1;
            float v2 = acc[fm][fn][2] + b0, v3 = acc[fm][fn][3] + b1;
            if (ACT) { v0=lrelu(v0); v1=lrelu(v1); v2=lrelu(v2); v3=lrelu(v3); }
            *(float2*)&C[(size_t)row*N + col]     = make_float2(v0, v1);
            *(float2*)&C[(size_t)(row+8)*N + col] = make_float2(v2, v3);
        }
    }
}

// ---------------- tensor-core GAT attention (separable exp + bf16 split) ----------------
template<int F>
__global__ void __launch_bounds__(256) k_attn(
    const float* __restrict__ wh, const float* __restrict__ src,
    const float* __restrict__ dst, const uint32_t* __restrict__ adjmask,
    float* __restrict__ out, int WS, int H)
{
    extern __shared__ char sm[];
    float* Df  = (float*)(sm);
    float* Pf  = (float*)(sm + 2048);
    float* Qf  = (float*)(sm + 4096);
    float* sS  = (float*)(sm + 6144);
    float* sP  = (float*)(sm + 6656);
    float* sQ  = (float*)(sm + 7168);
    float* Sum = (float*)(sm + 7680);
    float* pst = (float*)(sm + 8192);
    uint32_t* msk = (uint32_t*)(sm + 9216);
    uint32_t* Ath = (uint32_t*)(sm + 17408);
    uint32_t* Atl = (uint32_t*)(sm + 26624);
    uint32_t* Bh  = (uint32_t*)(sm + 35840);
    uint32_t* Bl  = (uint32_t*)(sm + 35840 + F*72);

    const int it = blockIdx.x, h = blockIdx.y, b = blockIdx.z;
    const int i0 = it*128;
    const int tid = threadIdx.x, w = tid >> 5, lane = tid & 31;
    const int r4 = lane >> 2, cl = lane & 3;
    const int whoff = h*64;

    constexpr int WM  = (F == 64) ? 32 : 64;
    constexpr int NWM = 128 / WM;
    constexpr int FM  = WM / 16;
    const int wm = w % NWM, wn = w / NWM;

    const float* dstb = dst + (size_t)(b*H + h)*512;
    const float* srcb = src + (size_t)(b*H + h)*512;
    for (int j = tid; j < 512; j += 256) {
        float d = dstb[j];
        Df[j] = d; Pf[j] = __expf(d); Qf[j] = __expf(0.2f*d);
    }
    if (tid < 128) {
        float s = srcb[i0 + tid];
        sS[tid] = s; sP[tid] = __expf(s); sQ[tid] = __expf(0.2f*s);
    }
    {
        const uint32_t* mb = adjmask + ((size_t)(b*512) + i0)*16;
        for (int s = tid; s < 2048; s += 256) msk[s] = mb[s];
    }

    float acc[FM][4][4];
    #pragma unroll
    for (int i = 0; i < FM; ++i)
        #pragma unroll
        for (int j = 0; j < 4; ++j)
            #pragma unroll
            for (int q = 0; q < 4; ++q) acc[i][j][q] = 0.f;

    const int ai = tid >> 1, half = tid & 1;
    __syncthreads();
    const float si = sS[ai], pie = sP[ai], qie = sQ[ai];
    float ps = 0.f;

    for (int c = 0; c < 16; ++c) {
        const int j0 = c*32;
        if (c) __syncthreads();
        {
            uint32_t mw = msk[ai*16 + c];
            #pragma unroll
            for (int jj = 0; jj < 8; ++jj) {
                int jl0 = half*16 + jj*2, jl1 = jl0 + 1;
                float v0 = 0.f, v1 = 0.f;
                if ((mw >> jl0) & 1u) {
                    int j = j0 + jl0;
                    v0 = (si + Df[j] > 0.f) ? pie*Pf[j] : qie*Qf[j];
                }
                if ((mw >> jl1) & 1u) {
                    int j = j0 + jl1;
                    v1 = (si + Df[j] > 0.f) ? pie*Pf[j] : qie*Qf[j];
                }
                ps += v0 + v1;
                uint32_t hw, lw; split2(v0, v1, hw, lw);
                int off = ai*18 + half*8 + jj;
                Ath[off] = hw; Atl[off] = lw;
            }
        }
        __nv_bfloat16* Bhb = (__nv_bfloat16*)Bh;
        __nv_bfloat16* Blb = (__nv_bfloat16*)Bl;
        if (F == 64) {
            const int f = tid & 63, jg = tid >> 6;
            #pragma unroll
            for (int jj = 0; jj < 8; ++jj) {
                int jl = jg*8 + jj;
                float v = wh[(size_t)(b*512 + j0 + jl)*WS + whoff + f];
                __nv_bfloat16 hv, lv; split1(v, hv, lv);
                Bhb[f*36 + jl] = hv; Blb[f*36 + jl] = lv;
            }
        } else {
            const int f = tid & 127, jg = tid >> 7;
            #pragma unroll
            for (int jj = 0; jj < 16; ++jj) {
                int jl = jg*16 + jj;
                float v = wh[(size_t)(b*512 + j0 + jl)*WS + whoff + f];
                __nv_bfloat16 hv, lv; split1(v, hv, lv);
                Bhb[f*36 + jl] = hv; Blb[f*36 + jl] = lv;
            }
        }
        __syncthreads();
        #pragma unroll
        for (int kk = 0; kk < 2; ++kk) {
            const int kw = kk*8;
            uint32_t ah[FM][4], al[FM][4];
            #pragma unroll
            for (int fm = 0; fm < FM; ++fm) {
                int base = (wm*WM + fm*16 + r4)*18 + kw + cl;
                ah[fm][0]=Ath[base];     ah[fm][1]=Ath[base+144];
                ah[fm][2]=Ath[base+4];   ah[fm][3]=Ath[base+148];
                al[fm][0]=Atl[base];     al[fm][1]=Atl[base+144];
                al[fm][2]=Atl[base+4];   al[fm][3]=Atl[base+148];
            }
            uint32_t bh[4][2], bl[4][2];
            #pragma unroll
            for (int fn = 0; fn < 4; ++fn) {
                int base = (wn*32 + fn*8 + r4)*18 + kw + cl;
                bh[fn][0]=Bh[base]; bh[fn][1]=Bh[base+4];
                bl[fn][0]=Bl[base]; bl[fn][1]=Bl[base+4];
            }
            #pragma unroll
            for (int fm = 0; fm < FM; ++fm)
                #pragma unroll
                for (int fn = 0; fn < 4; ++fn) {
                    mma16816(acc[fm][fn], ah[fm], bh[fn]);
                    mma16816(acc[fm][fn], ah[fm], bl[fn]);
                    mma16816(acc[fm][fn], al[fm], bh[fn]);
                }
        }
    }
    pst[tid] = ps;
    __syncthreads();
    if (tid < 128) Sum[tid] = pst[2*tid] + pst[2*tid+1];
    __syncthreads();
    #pragma unroll
    for (int fm = 0; fm < FM; ++fm) {
        int rl = wm*WM + fm*16 + r4;
        float S0 = Sum[rl],   i0v = (S0 > 0.f) ? 1.f/S0 : 0.f;
        float S1 = Sum[rl+8], i1v = (S1 > 0.f) ? 1.f/S1 : 0.f;
        #pragma unroll
        for (int fn = 0; fn < 4; ++fn) {
            int col = whoff + wn*32 + fn*8 + 2*cl;
            float v0 = eluf(acc[fm][fn][0] * i0v);
            float v1 = eluf(acc[fm][fn][1] * i0v);
            float v2 = eluf(acc[fm][fn][2] * i1v);
            float v3 = eluf(acc[fm][fn][3] * i1v);
            *(float2*)&out[(size_t)(b*512 + i0 + rl)*WS + col]     = make_float2(v0, v1);
            *(float2*)&out[(size_t)(b*512 + i0 + rl + 8)*WS + col] = make_float2(v2, v3);
        }
    }
}

// ---------------- src/dst score kernels ----------------
__global__ void k_srcdst1(const float* __restrict__ a_gat){
    const int row = blockIdx.x;
    const int b = row >> 9, n = row & 511;
    const int tid = threadIdx.x;
    __shared__ float wrow[256];
    wrow[tid] = g_wh1[(size_t)row*256 + tid];
    __syncthreads();
    const int w = tid >> 5, l = tid & 31;
    const int h = w >> 1, half = w & 1;
    float v = wrow[h*64 + l]      * a_gat[h*128 + half*64 + l]
            + wrow[h*64 + 32 + l] * a_gat[h*128 + half*64 + 32 + l];
    #pragma unroll
    for (int o = 16; o; o >>= 1) v += __shfl_down_sync(0xffffffffu, v, o);
    if (l == 0) {
        float* outp = half ? g_dst1 : g_src1;
        outp[(size_t)(b*4 + h)*512 + n] = v;
    }
}
__global__ void k_srcdst2(const float* __restrict__ a_go){
    const int row = blockIdx.x;
    const int tid = threadIdx.x;
    __shared__ float wrow[128];
    __shared__ float part[4];
    wrow[tid] = g_wh2[(size_t)row*128 + tid];
    __syncthreads();
    const int w = tid >> 5, l = tid & 31;
    const int which = w >> 1, p = w & 1;
    float v = wrow[p*64 + l]      * a_go[which*128 + p*64 + l]
            + wrow[p*64 + 32 + l] * a_go[which*128 + p*64 + 32 + l];
    #pragma unroll
    for (int o = 16; o; o >>= 1) v += __shfl_down_sync(0xffffffffu, v, o);
    if (l == 0) part[w] = v;
    __syncthreads();
    if (tid == 0) g_src2[row] = part[0] + part[1];
    if (tid == 1) g_dst2[row] = part[2] + part[3];
}

// ---------------- CNN ----------------
__global__ void k_conv1(const int* __restrict__ amino, const float* __restrict__ conv_b){
    const int l = blockIdx.x, b = blockIdx.y, f = threadIdx.x;
    float acc = conv_b[0];
    #pragma unroll
    for (int dl = 0; dl < 11; ++dl) {
        int l2 = l + dl - 5;
        if (l2 >= 0 && l2 < 1024) {
            int id = amino[b*1024 + l2];
            acc += g_T[((size_t)id*11 + dl)*128 + f];
        }
    }
    g_cnvA[((size_t)(b*1024) + l)*128 + f] = fmaxf(acc, 0.f);
}
// 11x11 SAME conv + bias + relu; two l-rows per thread packed into f32x2 lanes
__global__ void __launch_bounds__(256) k_conv(
    const float* __restrict__ in, float* __restrict__ out,
    const float* __restrict__ wsrc, const float* __restrict__ bsrc)
{
    __shared__ float tile[26*139];
    __shared__ float ws[121];
    const int lb = blockIdx.x * 16, b = blockIdx.y;
    const int tid = threadIdx.x;
    if (tid < 121) ws[tid] = wsrc[tid];
    for (int idx = tid; idx < 26*138; idx += 256) {
        const int r = idx / 138, c = idx % 138;
        const int gl = lb + r - 5, gf = c - 5;
        float v = 0.f;
        if (gl >= 0 && gl < 1024 && gf >= 0 && gf < 128)
            v = in[((size_t)(b*1024) + gl)*128 + gf];
        tile[r*139 + c] = v;
    }
    __syncthreads();
    const int fg = tid >> 3, lg = tid & 7;
    const int f0 = fg * 4;
    uint64_t accp[4];
    {
        uint64_t bp = pk2(bsrc[0]);
        accp[0]=bp; accp[1]=bp; accp[2]=bp; accp[3]=bp;
    }
    for (int dl = 0; dl < 11; ++dl) {
        const float* w  = ws + dl*11;
        const float* r0 = tile + (lg + dl)*139 + f0;
        const float* r1 = r0 + 8*139;
        uint64_t vp[14];
        #pragma unroll
        for (int j = 0; j < 14; ++j) vp[j] = pk2f(r0[j], r1[j]);
        #pragma unroll
        for (int df = 0; df < 11; ++df) {
            uint64_t wv = pk2(w[df]);
            fma2(accp[0], wv, vp[df+0]);
            fma2(accp[1], wv, vp[df+1]);
            fma2(accp[2], wv, vp[df+2]);
            fma2(accp[3], wv, vp[df+3]);
        }
    }
    float* o0 = out + ((size_t)(b*1024) + lb + lg)*128 + f0;
    float* o1 = o0 + 8*128;
    #pragma unroll
    for (int k = 0; k < 4; ++k) {
        float2 v = up2(accp[k]);
        o0[k] = fmaxf(v.x, 0.f);
        o1[k] = fmaxf(v.y, 0.f);
    }
}

// ---------------- masked mean pooling ----------------
__global__ void k_mean_part(const float* __restrict__ in, const float* __restrict__ mask,
                            int NNd){
    const int ch = blockIdx.x, b = blockIdx.y, f = threadIdx.x;
    const int rows = NNd / 8;
    const int r0 = ch * rows;
    float s = 0.f, m = 0.f;
    #pragma unroll 4
    for (int n = r0; n < r0 + rows; ++n) {
        float mk = mask[b*NNd + n];
        m += mk;
        s += mk * in[((size_t)b*NNd + n)*128 + f];
    }
    g_pp[(size_t)(b*8 + ch)*128 + f] = s;
    if (f == 0) g_pm[b*8 + ch] = m;
}
__global__ void k_mean_fin(float* __restrict__ outp){
    const int b = blockIdx.x, f = threadIdx.x;
    float s = 0.f, m = 0.f;
    #pragma unroll
    for (int ch = 0; ch < 8; ++ch) {
        s += g_pp[(size_t)(b*8 + ch)*128 + f];
        m += g_pm[b*8 + ch];
    }
    outp[b*128 + f] = s / m;
}

// ---------------- final predictor ----------------
__global__ void k_final(const float* __restrict__ pred_w, const float* __restrict__ pred_b,
                        float* __restrict__ out){
    __shared__ float red[256];
    const int b = blockIdx.x, c = threadIdx.x;
    float v = (c < 128) ? g_comp[b*128 + c] : g_prot[b*128 + (c - 128)];
    v = v > 0.f ? v : 0.04f*v;
    red[c] = v * pred_w[c];
    __syncthreads();
    for (int s = 128; s > 0; s >>= 1) {
        if (c < s) red[c] += red[c + s];
        __syncthreads();
    }
    if (c == 0) out[b] = red[0] + pred_b[0];
}

// ---------------- launch ----------------
extern "C" void kernel_launch(void* const* d_in, const int* in_sizes, int n_in,
                              void* d_out, int out_size)
{
    const int*   atoms      = (const int*)  d_in[0];
    const float* atoms_mask = (const float*)d_in[1];
    const int*   adj        = (const int*)  d_in[2];
    const int*   amino      = (const int*)  d_in[3];
    const float* amino_mask = (const float*)d_in[4];
    const float* E_atom     = (const float*)d_in[5];
    const float* E_amino    = (const float*)d_in[6];
    const float* W_gat      = (const float*)d_in[7];
    const float* a_gat      = (const float*)d_in[8];
    const float* W_go       = (const float*)d_in[9];
    const float* a_go       = (const float*)d_in[10];
    const float* W_comp_w   = (const float*)d_in[11];
    const float* W_comp_b   = (const float*)d_in[12];
    const float* conv_w     = (const float*)d_in[13];
    const float* conv_b     = (const float*)d_in[14];
    const float* W_att_w    = (const float*)d_in[15];
    const float* W_att_b    = (const float*)d_in[16];
    const float* pred_w     = (const float*)d_in[17];
    const float* pred_b     = (const float*)d_in[18];
    float* out = (float*)d_out;

    float *p_WcatT, *p_WgoT;
    float *p_av, *p_wh1, *p_multi, *p_wh2, *p_x, *p_atoms_vec, *p_av_att;
    float *p_src1, *p_dst1, *p_src2, *p_dst2, *p_cnvA, *p_cnvB, *p_comp, *p_prot;
    uint32_t* p_adjm;
    cudaGetSymbolAddress((void**)&p_WcatT, g_WcatT);
    cudaGetSymbolAddress((void**)&p_WgoT,  g_WgoT);
    cudaGetSymbolAddress((void**)&p_av,    g_av);
    cudaGetSymbolAddress((void**)&p_wh1,   g_wh1);
    cudaGetSymbolAddress((void**)&p_multi, g_multi);
    cudaGetSymbolAddress((void**)&p_wh2,   g_wh2);
    cudaGetSymbolAddress((void**)&p_x,     g_x);
    cudaGetSymbolAddress((void**)&p_atoms_vec, g_atoms_vec);
    cudaGetSymbolAddress((void**)&p_av_att, g_av_att);
    cudaGetSymbolAddress((void**)&p_src1,  g_src1);
    cudaGetSymbolAddress((void**)&p_dst1,  g_dst1);
    cudaGetSymbolAddress((void**)&p_src2,  g_src2);
    cudaGetSymbolAddress((void**)&p_dst2,  g_dst2);
    cudaGetSymbolAddress((void**)&p_cnvA,  g_cnvA);
    cudaGetSymbolAddress((void**)&p_cnvB,  g_cnvB);
    cudaGetSymbolAddress((void**)&p_comp,  g_comp);
    cudaGetSymbolAddress((void**)&p_prot,  g_prot);
    cudaGetSymbolAddress((void**)&p_adjm,  g_adjmask);

    const int SM_MM    = 55296;
    const int SM_AT64  = 35840 + 64*72*2;    // 45056
    const int SM_AT128 = 35840 + 128*72*2;   // 54272
    cudaFuncSetAttribute(k_mm<0>,    cudaFuncAttributeMaxDynamicSharedMemorySize, SM_MM);
    cudaFuncSetAttribute(k_mm<1>,    cudaFuncAttributeMaxDynamicSharedMemorySize, SM_MM);
    cudaFuncSetAttribute(k_attn<64>, cudaFuncAttributeMaxDynamicSharedMemorySize, SM_AT64);
    cudaFuncSetAttribute(k_attn<128>,cudaFuncAttributeMaxDynamicSharedMemorySize, SM_AT128);

    // fused prep (packadj + weight packs + conv table + atom embed)
    k_prep<<<20901, 256>>>(adj, W_gat, W_go, conv_w, E_amino, atoms, E_atom);

    // ---- compound branch ----
    k_mm<0><<<dim3(128, 2), 256, SM_MM>>>(p_av, p_WcatT, nullptr, p_wh1, 8192, 256, 128);
    k_srcdst1<<<BB*NN_, 256>>>(a_gat);
    k_attn<64><<<dim3(4, 4, BB), 256, SM_AT64>>>(p_wh1, p_src1, p_dst1, p_adjm, p_multi, 256, 4);
    k_mm<0><<<dim3(128, 1), 256, SM_MM>>>(p_multi, p_WgoT, nullptr, p_wh2, 8192, 128, 256);
    k_srcdst2<<<BB*NN_, 128>>>(a_go);
    k_attn<128><<<dim3(4, 1, BB), 256, SM_AT128>>>(p_wh2, p_src2, p_dst2, p_adjm, p_x, 128, 1);
    k_mm<1><<<dim3(128, 1), 256, SM_MM>>>(p_x, W_comp_w, W_comp_b, p_atoms_vec, 8192, 128, 128);
    k_mm<1><<<dim3(128, 1), 256, SM_MM>>>(p_atoms_vec, W_att_w, W_att_b, p_av_att, 8192, 128, 128);
    k_mean_part<<<dim3(8, BB), 128>>>(p_av_att, atoms_mask, NN_);
    k_mean_fin<<<BB, 128>>>(p_comp);

    // ---- protein branch ----
    k_conv1<<<dim3(LL, BB), 128>>>(amino, conv_b);
    k_conv<<<dim3(64, BB), 256>>>(p_cnvA, p_cnvB, conv_w + 121,   conv_b + 1);
    k_conv<<<dim3(64, BB), 256>>>(p_cnvB, p_cnvA, conv_w + 2*121, conv_b + 2);
    k_mm<1><<<dim3(256, 1), 256, SM_MM>>>(p_cnvA, W_att_w, W_att_b, p_cnvB, 16384, 128, 128);
    k_mean_part<<<dim3(8, BB), 128>>>(p_cnvB, amino_mask, LL);
    k_mean_fin<<<BB, 128>>>(p_prot);

    // ---- head ----
    k_final<<<BB, 256>>>(pred_w, pred_b, out);
}